// round 1
// baseline (speedup 1.0000x reference)
#include <cuda_runtime.h>
#include <cuda_bf16.h>
#include <cstdint>

// Problem constants
#define BV   32      // B*V
#define SEQ  512
#define EMB  1024
#define NH   16
#define DH   64
#define M_ROWS (BV*SEQ)      // 16384
#define QKV_N  (3*EMB)       // 3072

// Scratch (allocation-free rule: __device__ globals)
// g_qkv layout: [3][BV][NH][SEQ][DH]
__device__ float g_qkv[(size_t)3 * BV * NH * SEQ * DH];
// g_attn layout: [BV][SEQ][EMB]  (column = h*64 + d)
__device__ float g_attn[(size_t)BV * SEQ * EMB];

// ---------------------------------------------------------------------------
// Generic tiled fp32 GEMM: C = A[M,K] @ W[K,N] + bias[N]
// 64x64 block tile, BK=16, 256 threads, 4x4 per-thread microtile.
// MODE 0: plain row-major store.  MODE 1: scatter into g_qkv layout.
// Assumes M%64==0, N%64==0, K%16==0 (true for all calls here).
// ---------------------------------------------------------------------------
template <int MODE>
__global__ void __launch_bounds__(256) gemm64(const float* __restrict__ A,
                                              const float* __restrict__ W,
                                              const float* __restrict__ bias,
                                              float* __restrict__ C,
                                              int M, int N, int K) {
    __shared__ float As[16][65];   // [k][m], padded vs STS bank conflicts
    __shared__ float Bs[16][64];   // [k][n]

    const int tid = threadIdx.x;
    const int tx = tid & 15;       // n direction
    const int ty = tid >> 4;       // m direction
    const int m0 = blockIdx.y * 64;
    const int n0 = blockIdx.x * 64;

    float acc[4][4];
#pragma unroll
    for (int i = 0; i < 4; i++)
#pragma unroll
        for (int j = 0; j < 4; j++) acc[i][j] = 0.f;

    for (int k0 = 0; k0 < K; k0 += 16) {
#pragma unroll
        for (int i = 0; i < 4; i++) {
            int idx = tid + 256 * i;            // 0..1023
            int am = idx >> 4, ak = idx & 15;   // A tile 64x16
            As[ak][am] = A[(size_t)(m0 + am) * K + k0 + ak];
            int bk = idx >> 6, bn = idx & 63;   // B tile 16x64
            Bs[bk][bn] = W[(size_t)(k0 + bk) * N + n0 + bn];
        }
        __syncthreads();

#pragma unroll
        for (int kk = 0; kk < 16; kk++) {
            float a[4], b[4];
#pragma unroll
            for (int i = 0; i < 4; i++) a[i] = As[kk][ty * 4 + i];
            float4 bv4 = *reinterpret_cast<const float4*>(&Bs[kk][tx * 4]);
            b[0] = bv4.x; b[1] = bv4.y; b[2] = bv4.z; b[3] = bv4.w;
#pragma unroll
            for (int i = 0; i < 4; i++)
#pragma unroll
                for (int j = 0; j < 4; j++) acc[i][j] += a[i] * b[j];
        }
        __syncthreads();
    }

#pragma unroll
    for (int i = 0; i < 4; i++) {
#pragma unroll
        for (int j = 0; j < 4; j++) {
            int r = m0 + ty * 4 + i;
            int c = n0 + tx * 4 + j;
            float v = acc[i][j] + bias[c];
            if (MODE == 0) {
                C[(size_t)r * N + c] = v;
            } else {
                // column split order is (qkv, d, h): c = qkv*1024 + d*16 + h
                int qkv = c >> 10;
                int rem = c & 1023;
                int d = rem >> 4;
                int h = rem & 15;
                int bv = r >> 9;       // / SEQ
                int s = r & 511;       // % SEQ
                size_t dst = ((((size_t)qkv * BV + bv) * NH + h) * SEQ + s) * DH + d;
                C[dst] = v;
            }
        }
    }
}

// ---------------------------------------------------------------------------
// Attention: one thread = one query row. q, acc register-resident (D=64).
// K/V tiles of 32 rows staged in SMEM. Online softmax.
// grid: (SEQ/64, BV*NH), block: 64 threads.
// Output written as (bv, s, h*64+d) so the output GEMM is a plain GEMM.
// ---------------------------------------------------------------------------
#define KV_TILE 32

__global__ void __launch_bounds__(64) attn_kernel(const float* __restrict__ qkvbuf,
                                                  float* __restrict__ out) {
    const int q_idx = blockIdx.x * 64 + threadIdx.x;
    const int bvh = blockIdx.y;
    const int bv = bvh >> 4;
    const int h  = bvh & 15;

    const size_t head = ((size_t)bv * NH + h) * SEQ * DH;
    const float* Q = qkvbuf + head;
    const float* K = qkvbuf + (size_t)1 * BV * NH * SEQ * DH + head;
    const float* V = qkvbuf + (size_t)2 * BV * NH * SEQ * DH + head;

    __shared__ float Ks[KV_TILE][DH];
    __shared__ float Vs[KV_TILE][DH];

    float qreg[DH], acc[DH];
    const float scale = 0.125f;  // 1/sqrt(64)
#pragma unroll
    for (int i = 0; i < 16; i++) {
        float4 t = reinterpret_cast<const float4*>(Q + (size_t)q_idx * DH)[i];
        qreg[4 * i + 0] = t.x * scale;
        qreg[4 * i + 1] = t.y * scale;
        qreg[4 * i + 2] = t.z * scale;
        qreg[4 * i + 3] = t.w * scale;
    }
#pragma unroll
    for (int d = 0; d < DH; d++) acc[d] = 0.f;

    float m = -1e30f, l = 0.f;

    for (int kv0 = 0; kv0 < SEQ; kv0 += KV_TILE) {
        // cooperative tile load: 32x64 floats = 512 float4, 64 threads x 8
#pragma unroll
        for (int i = 0; i < 8; i++) {
            int idx = threadIdx.x + 64 * i;
            reinterpret_cast<float4*>(&Ks[0][0])[idx] =
                reinterpret_cast<const float4*>(K + (size_t)kv0 * DH)[idx];
            reinterpret_cast<float4*>(&Vs[0][0])[idx] =
                reinterpret_cast<const float4*>(V + (size_t)kv0 * DH)[idx];
        }
        __syncthreads();

        float sc[KV_TILE];
        float tmax = -1e30f;
#pragma unroll
        for (int j = 0; j < KV_TILE; j++) {
            float s = 0.f;
#pragma unroll
            for (int d = 0; d < DH; d++) s += qreg[d] * Ks[j][d];
            sc[j] = s;
            tmax = fmaxf(tmax, s);
        }

        float mnew = fmaxf(m, tmax);
        float corr = __expf(m - mnew);
        l *= corr;
#pragma unroll
        for (int d = 0; d < DH; d++) acc[d] *= corr;
#pragma unroll
        for (int j = 0; j < KV_TILE; j++) {
            float p = __expf(sc[j] - mnew);
            l += p;
#pragma unroll
            for (int d = 0; d < DH; d++) acc[d] += p * Vs[j][d];
        }
        m = mnew;
        __syncthreads();
    }

    const float inv_l = 1.f / l;
    float* dst = out + ((size_t)bv * SEQ + q_idx) * EMB + h * DH;
#pragma unroll
    for (int i = 0; i < 16; i++) {
        float4 t;
        t.x = acc[4 * i + 0] * inv_l;
        t.y = acc[4 * i + 1] * inv_l;
        t.z = acc[4 * i + 2] * inv_l;
        t.w = acc[4 * i + 3] * inv_l;
        reinterpret_cast<float4*>(dst)[i] = t;
    }
}

// ---------------------------------------------------------------------------
extern "C" void kernel_launch(void* const* d_in, const int* in_sizes, int n_in,
                              void* d_out, int out_size) {
    const float* x    = (const float*)d_in[0];  // (B,V,S,E) = (16384, 1024)
    const float* Wqkv = (const float*)d_in[1];  // (1024, 3072)
    const float* bqkv = (const float*)d_in[2];  // (3072,)
    const float* Wo   = (const float*)d_in[3];  // (1024, 1024)
    const float* bo   = (const float*)d_in[4];  // (1024,)
    float* out = (float*)d_out;

    float* qkvbuf;
    float* attnbuf;
    cudaGetSymbolAddress((void**)&qkvbuf, g_qkv);
    cudaGetSymbolAddress((void**)&attnbuf, g_attn);

    // 1) QKV GEMM + scatter into (qkv, bv, h, s, d)
    {
        dim3 grid(QKV_N / 64, M_ROWS / 64);
        gemm64<1><<<grid, 256>>>(x, Wqkv, bqkv, qkvbuf, M_ROWS, QKV_N, EMB);
    }
    // 2) Attention
    {
        dim3 grid(SEQ / 64, BV * NH);
        attn_kernel<<<grid, 64>>>(qkvbuf, attnbuf);
    }
    // 3) Output projection
    {
        dim3 grid(EMB / 64, M_ROWS / 64);
        gemm64<0><<<grid, 256>>>(attnbuf, Wo, bo, out, M_ROWS, EMB, EMB);
    }
}

// round 11
// speedup vs baseline: 1.8217x; 1.8217x over previous
#include <cuda_runtime.h>
#include <cuda_bf16.h>
#include <cstdint>

#define BV   32
#define SEQ  512
#define EMB  1024
#define NH   16
#define DH   64
#define MROWS (BV*SEQ)      // 16384
#define QKVN  (3*EMB)       // 3072

typedef unsigned long long ull;

// ---------------- scratch (__device__ globals; no allocs allowed) ----------
// g_qkv layout: [bv*s][3072] row-major; columns pre-permuted to qkv*1024 + h*64 + d
__device__ float         g_qkv [(size_t)MROWS*QKVN];
__device__ float         g_bq  [QKVN];                      // permuted qkv bias
__device__ __nv_bfloat16 g_xh [(size_t)MROWS*EMB];
__device__ __nv_bfloat16 g_xl [(size_t)MROWS*EMB];
__device__ __nv_bfloat16 g_ah [(size_t)MROWS*EMB];
__device__ __nv_bfloat16 g_al [(size_t)MROWS*EMB];
__device__ __nv_bfloat16 g_wqh[(size_t)QKVN*EMB];           // [N][K], rows permuted
__device__ __nv_bfloat16 g_wql[(size_t)QKVN*EMB];
__device__ __nv_bfloat16 g_woh[(size_t)EMB*EMB];            // [N][K]
__device__ __nv_bfloat16 g_wol[(size_t)EMB*EMB];

// ---------------- helpers ----------------
__device__ __forceinline__ uint32_t smem_to_u32(const void* p) {
    uint32_t a;
    asm("{ .reg .u64 t; cvta.to.shared.u64 t, %1; cvt.u32.u64 %0, t; }" : "=r"(a) : "l"(p));
    return a;
}
__device__ __forceinline__ void cpa16(uint32_t dst, const void* src) {
    asm volatile("cp.async.cg.shared.global [%0], [%1], 16;" :: "r"(dst), "l"(src) : "memory");
}
#define CP_COMMIT() asm volatile("cp.async.commit_group;" ::: "memory")
#define CP_WAIT0()  asm volatile("cp.async.wait_group 0;" ::: "memory")

#define LDSM_X4(r, addr) \
    asm volatile("ldmatrix.sync.aligned.m8n8.x4.shared.b16 {%0,%1,%2,%3}, [%4];" \
        : "=r"((r)[0]), "=r"((r)[1]), "=r"((r)[2]), "=r"((r)[3]) : "r"(addr))
#define LDSM_X2(r, addr) \
    asm volatile("ldmatrix.sync.aligned.m8n8.x2.shared.b16 {%0,%1}, [%2];" \
        : "=r"((r)[0]), "=r"((r)[1]) : "r"(addr))

#define MMA16816(d, a, b) \
    asm volatile("mma.sync.aligned.m16n8k16.row.col.f32.bf16.bf16.f32 " \
        "{%0,%1,%2,%3},{%4,%5,%6,%7},{%8,%9},{%0,%1,%2,%3};" \
        : "+f"((d)[0]), "+f"((d)[1]), "+f"((d)[2]), "+f"((d)[3]) \
        : "r"((a)[0]), "r"((a)[1]), "r"((a)[2]), "r"((a)[3]), "r"((b)[0]), "r"((b)[1]))

// packed f32x2 (validated by ptxas in round 10 — no errors on these lines)
#define FMA_F32X2(d, a, b, c) asm("fma.rn.f32x2 %0, %1, %2, %3;" : "=l"(d) : "l"(a), "l"(b), "l"(c))
#define MUL_F32X2(d, a, b)    asm("mul.rn.f32x2 %0, %1, %2;" : "=l"(d) : "l"(a), "l"(b))
__device__ __forceinline__ ull pack2(float x, float y) {
    ull r; asm("mov.b64 %0, {%1, %2};" : "=l"(r) : "f"(x), "f"(y)); return r;
}
__device__ __forceinline__ void unpack2(ull v, float& x, float& y) {
    asm("mov.b64 {%0, %1}, %2;" : "=f"(x), "=f"(y) : "l"(v));
}

__device__ __forceinline__ void split_hl(float x, __nv_bfloat16& h, __nv_bfloat16& l) {
    h = __float2bfloat16(x);
    l = __float2bfloat16(x - __bfloat162float(h));
}

// column permutation for the QKV projection: n = qkv*1024 + d*16 + h  ->  qkv*1024 + h*64 + d
__host__ __device__ __forceinline__ int qkv_perm(int n) {
    int d = (n >> 4) & 63;
    int h = n & 15;
    return (n & ~1023) | (h << 6) | d;
}

// ---------------------------------------------------------------------------
// Prep kernels
// ---------------------------------------------------------------------------
__global__ void __launch_bounds__(256) conv_hl(const float* __restrict__ X,
                                               __nv_bfloat16* __restrict__ Xh,
                                               __nv_bfloat16* __restrict__ Xl) {
    size_t i = ((size_t)blockIdx.x * 256 + threadIdx.x) * 4;
    float4 v = *(const float4*)(X + i);
    __nv_bfloat16 h0, h1, h2, h3, l0, l1, l2, l3;
    split_hl(v.x, h0, l0); split_hl(v.y, h1, l1);
    split_hl(v.z, h2, l2); split_hl(v.w, h3, l3);
    __nv_bfloat162 a, b, c, d;
    a.x = h0; a.y = h1; b.x = h2; b.y = h3;
    c.x = l0; c.y = l1; d.x = l2; d.y = l3;
    ((__nv_bfloat162*)(Xh + i))[0] = a; ((__nv_bfloat162*)(Xh + i))[1] = b;
    ((__nv_bfloat162*)(Xl + i))[0] = c; ((__nv_bfloat162*)(Xl + i))[1] = d;
}

// W[K][N] fp32 -> T[N'][K] bf16 hi/lo (N' = permuted row for PERM=1)
template <int PERM>
__global__ void transpose_conv(const float* __restrict__ W,
                               __nv_bfloat16* __restrict__ Th,
                               __nv_bfloat16* __restrict__ Tl,
                               int K, int N) {
    __shared__ float t[32][33];
    int n0 = blockIdx.x * 32, k0 = blockIdx.y * 32;
    int tx = threadIdx.x, ty = threadIdx.y;
#pragma unroll
    for (int i = 0; i < 32; i += 8)
        t[ty + i][tx] = W[(size_t)(k0 + ty + i) * N + n0 + tx];
    __syncthreads();
#pragma unroll
    for (int i = 0; i < 32; i += 8) {
        float x = t[tx][ty + i];                     // W[k0+tx][n0+ty+i]
        __nv_bfloat16 h, l; split_hl(x, h, l);
        int n = n0 + ty + i;
        int outn = PERM ? qkv_perm(n) : n;
        size_t o = (size_t)outn * K + k0 + tx;
        Th[o] = h; Tl[o] = l;
    }
}

__global__ void perm_bias(const float* __restrict__ b, float* __restrict__ bp) {
    int n = blockIdx.x * 1024 + threadIdx.x;
    bp[qkv_perm(n)] = b[n];
}

// ---------------------------------------------------------------------------
// mma.sync bf16 GEMM (compute_103-safe): C = (Ah+Al)[M,K] @ (Bh+Bl)[N,K]^T + bias
// 128x128x32 tile, 256 thr, 8 warps (2m x 4n), per-warp 64x32 via m16n8k16.
// hi/lo 3-pass: Ah*Bh + Ah*Bl + Al*Bh.
// ---------------------------------------------------------------------------
#define LDT 40   // padded smem row stride in bf16 (80 bytes = 20 banks -> ldmatrix conflict-free)

__global__ void __launch_bounds__(256) tgemm(const __nv_bfloat16* __restrict__ Ah,
                                             const __nv_bfloat16* __restrict__ Al,
                                             const __nv_bfloat16* __restrict__ Bh,
                                             const __nv_bfloat16* __restrict__ Bl,
                                             const float* __restrict__ bias,
                                             float* __restrict__ C,
                                             int M, int N, int K) {
    __shared__ __nv_bfloat16 sAh[128 * LDT], sAl[128 * LDT];
    __shared__ __nv_bfloat16 sBh[128 * LDT], sBl[128 * LDT];

    const int tid = threadIdx.x, wid = tid >> 5, lane = tid & 31;
    const int warp_m = wid & 1, warp_n = wid >> 1;
    const int m0 = blockIdx.y * 128, n0 = blockIdx.x * 128;

    const uint32_t uAh = smem_to_u32(sAh), uAl = smem_to_u32(sAl);
    const uint32_t uBh = smem_to_u32(sBh), uBl = smem_to_u32(sBl);

    // per-lane ldmatrix byte offsets within a tile
    const uint32_t aoff = (uint32_t)((warp_m * 64 + (lane & 15)) * 80 + (lane >> 4) * 16);
    const uint32_t boff = (uint32_t)((warp_n * 32 + (lane & 7)) * 80 + ((lane >> 3) & 1) * 16);

    float acc[4][4][4];
#pragma unroll
    for (int mi = 0; mi < 4; mi++)
#pragma unroll
        for (int ni = 0; ni < 4; ni++)
#pragma unroll
            for (int j = 0; j < 4; j++) acc[mi][ni][j] = 0.f;

    const int nstage = K >> 5;
    for (int stage = 0; stage < nstage; stage++) {
        const int k0 = stage << 5;
        // stage 4 tiles of 128x32 bf16 (each 512 x 16B chunks; 256 thr x 2)
#pragma unroll
        for (int i = 0; i < 2; i++) {
            int idx = tid + 256 * i;
            int rr = idx >> 2, cc = idx & 3;
            uint32_t dst = (uint32_t)(rr * 80 + cc * 16);
            size_t ao = (size_t)(m0 + rr) * K + k0 + cc * 8;
            size_t bo = (size_t)(n0 + rr) * K + k0 + cc * 8;
            cpa16(uAh + dst, Ah + ao);
            cpa16(uAl + dst, Al + ao);
            cpa16(uBh + dst, Bh + bo);
            cpa16(uBl + dst, Bl + bo);
        }
        CP_COMMIT(); CP_WAIT0();
        __syncthreads();

#pragma unroll
        for (int kk = 0; kk < 2; kk++) {
            const uint32_t kb = kk * 32;   // 16 bf16 = 32 bytes
            uint32_t a[4][4], bh[4][2], bl[4][2];
#pragma unroll
            for (int mi = 0; mi < 4; mi++)
                LDSM_X4(a[mi], uAh + aoff + mi * (16 * 80) + kb);
#pragma unroll
            for (int ni = 0; ni < 4; ni++) {
                LDSM_X2(bh[ni], uBh + boff + ni * (8 * 80) + kb);
                LDSM_X2(bl[ni], uBl + boff + ni * (8 * 80) + kb);
            }
            // pass 1: Ah * Bh
#pragma unroll
            for (int mi = 0; mi < 4; mi++)
#pragma unroll
                for (int ni = 0; ni < 4; ni++) MMA16816(acc[mi][ni], a[mi], bh[ni]);
            // pass 2: Ah * Bl
#pragma unroll
            for (int mi = 0; mi < 4; mi++)
#pragma unroll
                for (int ni = 0; ni < 4; ni++) MMA16816(acc[mi][ni], a[mi], bl[ni]);
            // pass 3: Al * Bh (reload a from Al)
#pragma unroll
            for (int mi = 0; mi < 4; mi++)
                LDSM_X4(a[mi], uAl + aoff + mi * (16 * 80) + kb);
#pragma unroll
            for (int mi = 0; mi < 4; mi++)
#pragma unroll
                for (int ni = 0; ni < 4; ni++) MMA16816(acc[mi][ni], a[mi], bh[ni]);
        }
        __syncthreads();
    }

    // epilogue: d0/d1 at (row lane/4, col 2*(lane%4)+{0,1}); d2/d3 at row+8
    const int row0 = m0 + warp_m * 64 + (lane >> 2);
    const int col0 = n0 + warp_n * 32 + 2 * (lane & 3);
#pragma unroll
    for (int mi = 0; mi < 4; mi++) {
#pragma unroll
        for (int ni = 0; ni < 4; ni++) {
            int rw = row0 + mi * 16;
            int cw = col0 + ni * 8;
            float b0 = bias[cw], b1 = bias[cw + 1];
            float2 v0, v1;
            v0.x = acc[mi][ni][0] + b0; v0.y = acc[mi][ni][1] + b1;
            v1.x = acc[mi][ni][2] + b0; v1.y = acc[mi][ni][3] + b1;
            *(float2*)(C + (size_t)rw * N + cw) = v0;
            *(float2*)(C + (size_t)(rw + 8) * N + cw) = v1;
        }
    }
}

// ---------------------------------------------------------------------------
// Attention: 1 thread = 1 query row, packed f32x2 math. grid (8, 512), 64 thr.
// Reads qkv as [bv*s][3072] with cols (qkv, h*64+d). Writes hi/lo bf16.
// ---------------------------------------------------------------------------
#define KV_TILE 32

__global__ void __launch_bounds__(64) attn_kernel(const float* __restrict__ qkvbuf,
                                                  __nv_bfloat16* __restrict__ outh,
                                                  __nv_bfloat16* __restrict__ outl) {
    const int q_idx = blockIdx.x * 64 + threadIdx.x;
    const int bvh = blockIdx.y;
    const int bv = bvh >> 4, h = bvh & 15;

    const size_t rowbase = (size_t)bv * SEQ;
    const int hoff = h * DH;

    __shared__ float Ks[KV_TILE][DH];
    __shared__ float Vs[KV_TILE][DH];

    ull q2[32], a2[32];
    const float scale = 0.125f;  // 1/sqrt(64)
    {
        const float4* Qrow = (const float4*)(qkvbuf + (rowbase + q_idx) * QKVN + hoff);
#pragma unroll
        for (int i = 0; i < 16; i++) {
            float4 t = Qrow[i];
            q2[2 * i + 0] = pack2(t.x * scale, t.y * scale);
            q2[2 * i + 1] = pack2(t.z * scale, t.w * scale);
        }
    }
    const ull zero2 = pack2(0.f, 0.f);
#pragma unroll
    for (int i = 0; i < 32; i++) a2[i] = zero2;

    float m = -1e30f, l = 0.f;

    for (int kv0 = 0; kv0 < SEQ; kv0 += KV_TILE) {
        // coop tile load: 32 rows x 16 float4; threads 0-15 cover one row (256B)
#pragma unroll
        for (int i = 0; i < 8; i++) {
            int idx = threadIdx.x + 64 * i;
            int j = idx >> 4, f = idx & 15;
            const float* krow = qkvbuf + (rowbase + kv0 + j) * QKVN + EMB + hoff;
            const float* vrow = qkvbuf + (rowbase + kv0 + j) * QKVN + 2 * EMB + hoff;
            ((float4*)&Ks[j][0])[f] = ((const float4*)krow)[f];
            ((float4*)&Vs[j][0])[f] = ((const float4*)vrow)[f];
        }
        __syncthreads();

        float sc[KV_TILE];
        float tmax = -1e30f;
#pragma unroll
        for (int j = 0; j < KV_TILE; j++) {
            const ull* krow = reinterpret_cast<const ull*>(&Ks[j][0]);
            ull s2 = zero2;
#pragma unroll
            for (int i = 0; i < 32; i++) FMA_F32X2(s2, q2[i], krow[i], s2);
            float sa, sb; unpack2(s2, sa, sb);
            sc[j] = sa + sb;
            tmax = fmaxf(tmax, sc[j]);
        }

        float mnew = fmaxf(m, tmax);
        float corr = __expf(m - mnew);
        l *= corr;
        const ull corr2 = pack2(corr, corr);
#pragma unroll
        for (int i = 0; i < 32; i++) MUL_F32X2(a2[i], corr2, a2[i]);
#pragma unroll
        for (int j = 0; j < KV_TILE; j++) {
            float p = __expf(sc[j] - mnew);
            l += p;
            const ull p2 = pack2(p, p);
            const ull* vrow = reinterpret_cast<const ull*>(&Vs[j][0]);
#pragma unroll
            for (int i = 0; i < 32; i++) FMA_F32X2(a2[i], p2, vrow[i], a2[i]);
        }
        m = mnew;
        __syncthreads();
    }

    const float inv_l = 1.f / l;
    const size_t rowoff = (rowbase + q_idx) * EMB + hoff;
    __nv_bfloat162* dh2 = reinterpret_cast<__nv_bfloat162*>(outh + rowoff);
    __nv_bfloat162* dl2 = reinterpret_cast<__nv_bfloat162*>(outl + rowoff);
#pragma unroll
    for (int i = 0; i < 32; i++) {
        float x, y;
        unpack2(a2[i], x, y);
        x *= inv_l; y *= inv_l;
        __nv_bfloat16 hx, lx, hy, ly;
        split_hl(x, hx, lx); split_hl(y, hy, ly);
        __nv_bfloat162 ph, pl;
        ph.x = hx; ph.y = hy;
        pl.x = lx; pl.y = ly;
        dh2[i] = ph;
        dl2[i] = pl;
    }
}

// ---------------------------------------------------------------------------
extern "C" void kernel_launch(void* const* d_in, const int* in_sizes, int n_in,
                              void* d_out, int out_size) {
    const float* x    = (const float*)d_in[0];
    const float* Wqkv = (const float*)d_in[1];
    const float* bqkv = (const float*)d_in[2];
    const float* Wo   = (const float*)d_in[3];
    const float* bo   = (const float*)d_in[4];
    float* out = (float*)d_out;

    float *qkvbuf, *bq;
    __nv_bfloat16 *xh, *xl, *ah, *al, *wqh, *wql, *woh, *wol;
    cudaGetSymbolAddress((void**)&qkvbuf, g_qkv);
    cudaGetSymbolAddress((void**)&bq,  g_bq);
    cudaGetSymbolAddress((void**)&xh,  g_xh);  cudaGetSymbolAddress((void**)&xl,  g_xl);
    cudaGetSymbolAddress((void**)&ah,  g_ah);  cudaGetSymbolAddress((void**)&al,  g_al);
    cudaGetSymbolAddress((void**)&wqh, g_wqh); cudaGetSymbolAddress((void**)&wql, g_wql);
    cudaGetSymbolAddress((void**)&woh, g_woh); cudaGetSymbolAddress((void**)&wol, g_wol);

    // prep
    conv_hl<<<(MROWS * EMB) / 1024, 256>>>(x, xh, xl);
    {
        dim3 g(QKVN / 32, EMB / 32); dim3 b(32, 8);
        transpose_conv<1><<<g, b>>>(Wqkv, wqh, wql, EMB, QKVN);   // rows permuted
    }
    {
        dim3 g(EMB / 32, EMB / 32); dim3 b(32, 8);
        transpose_conv<0><<<g, b>>>(Wo, woh, wol, EMB, EMB);
    }
    perm_bias<<<QKVN / 1024, 1024>>>(bqkv, bq);

    // QKV projection (tensor cores via mma.sync) -> [MROWS][3072], cols permuted
    {
        dim3 grid(QKVN / 128, MROWS / 128);
        tgemm<<<grid, 256>>>(xh, xl, wqh, wql, bq, qkvbuf, MROWS, QKVN, EMB);
    }
    // attention (writes hi/lo bf16 directly)
    {
        dim3 grid(SEQ / 64, BV * NH);
        attn_kernel<<<grid, 64>>>(qkvbuf, ah, al);
    }
    // output projection
    {
        dim3 grid(EMB / 128, MROWS / 128);
        tgemm<<<grid, 256>>>(ah, al, woh, wol, bo, out, MROWS, EMB, EMB);
    }
}